// round 1
// baseline (speedup 1.0000x reference)
#include <cuda_runtime.h>
#include <math.h>

#define BB 16
#define AA 1024
#define TT 512
#define DD 256
#define TWOD 512
#define NROWS_A (BB*AA)            /* 16384 article rows  */
#define NROWS_T (BB*TT)            /* 8192 template rows  */
#define NROWS   (NROWS_A+NROWS_T)  /* 24576 total rows    */

// Scratch (static device allocation — permitted; runtime alloc is not)
__device__ float g_buf0[(size_t)NROWS * DD];
__device__ float g_buf1[(size_t)NROWS * DD];
__device__ float g_sq[NROWS];
__device__ float g_rowmax[NROWS_A];

// ---------------------------------------------------------------------------
// Embedding gather: rows [0,16384) = article, [16384,24576) = template
// ---------------------------------------------------------------------------
__global__ void embed_kernel(const int* __restrict__ aw, const int* __restrict__ tw,
                             const float* __restrict__ emb) {
    int gi  = blockIdx.x * blockDim.x + threadIdx.x;   // float4 index
    int row = gi >> 6;
    int c4  = gi & 63;
    int word = (row < NROWS_A) ? aw[row] : tw[row - NROWS_A];
    ((float4*)g_buf0)[row * 64 + c4] = ((const float4*)emb)[word * 64 + c4];
}

// ---------------------------------------------------------------------------
// Fused res-block: y = conv1d_dilated(x) + b; a,g = split(y); out = x + a*sigmoid(g)
// Implicit GEMM: out tile 64(L) x 64(channel-pairs), reduction over 3*256.
// grid.x: 384 tiles (256 article + 128 template), grid.y: 4 channel groups.
// ---------------------------------------------------------------------------
__global__ __launch_bounds__(256, 2) void conv_glu_kernel(
    const float* __restrict__ xin, float* __restrict__ xout,
    const float* __restrict__ w, const float* __restrict__ bias, int dil)
{
    int t = blockIdx.x, cg = blockIdx.y;
    int base, l0, L;
    if (t < 256) { int s = t >> 4; l0 = (t & 15) << 6; base = s * AA;            L = AA; }
    else         { int s = (t-256) >> 3; l0 = ((t-256) & 7) << 6; base = NROWS_A + s * TT; L = TT; }

    const int tid = threadIdx.x;
    const int tx = tid & 15, ty = tid >> 4;
    const int cb = cg << 6;

    __shared__ __align__(16) float xs[64][33];   // [l][dchunk], padded
    __shared__ __align__(16) float was[32][64];  // [dchunk][col] for 'a'
    __shared__ __align__(16) float wgs[32][64];  // [dchunk][col] for 'g'

    float acc_a[4][4] = {};
    float acc_g[4][4] = {};

    for (int k = 0; k < 3; ++k) {
        const int off = (k - 1) * dil;
        for (int dc = 0; dc < DD; dc += 32) {
            // load x chunk (zero-padded at sequence boundary)
            #pragma unroll
            for (int s = 0; s < 8; ++s) {
                int e = tid + s * 256;
                int l = e >> 5, c = e & 31;
                int lg = l0 + l + off;
                float v = 0.f;
                if (lg >= 0 && lg < L) v = xin[(base + lg) * DD + dc + c];
                xs[l][c] = v;
            }
            // load weight chunks for both halves of the GLU
            #pragma unroll
            for (int s = 0; s < 2; ++s) {
                int fi = tid + s * 256;
                int r = fi >> 4, c4 = (fi & 15) << 2;
                const float* wr = w + (size_t)((k * DD) + dc + r) * TWOD + cb + c4;
                *(float4*)&was[r][c4] = *(const float4*)wr;
                *(float4*)&wgs[r][c4] = *(const float4*)(wr + DD);
            }
            __syncthreads();
            #pragma unroll
            for (int dd = 0; dd < 32; ++dd) {
                float xr[4];
                #pragma unroll
                for (int i = 0; i < 4; ++i) xr[i] = xs[ty * 4 + i][dd];
                float4 a4 = *(const float4*)&was[dd][tx * 4];
                float4 g4 = *(const float4*)&wgs[dd][tx * 4];
                float wa[4] = {a4.x, a4.y, a4.z, a4.w};
                float wg[4] = {g4.x, g4.y, g4.z, g4.w};
                #pragma unroll
                for (int i = 0; i < 4; ++i)
                    #pragma unroll
                    for (int j = 0; j < 4; ++j) {
                        acc_a[i][j] = fmaf(xr[i], wa[j], acc_a[i][j]);
                        acc_g[i][j] = fmaf(xr[i], wg[j], acc_g[i][j]);
                    }
            }
            __syncthreads();
        }
    }

    float4 ba4 = *(const float4*)&bias[cb + tx * 4];
    float4 bg4 = *(const float4*)&bias[DD + cb + tx * 4];
    const float ba[4] = {ba4.x, ba4.y, ba4.z, ba4.w};
    const float bg[4] = {bg4.x, bg4.y, bg4.z, bg4.w};

    #pragma unroll
    for (int i = 0; i < 4; ++i) {
        int gr = base + l0 + ty * 4 + i;
        const float4 rx = *(const float4*)&xin[(size_t)gr * DD + cb + tx * 4];
        float4 o;
        float r[4] = {rx.x, rx.y, rx.z, rx.w};
        float ov[4];
        #pragma unroll
        for (int j = 0; j < 4; ++j) {
            float a = acc_a[i][j] + ba[j];
            float g = acc_g[i][j] + bg[j];
            float sg = 1.f / (1.f + expf(-g));
            ov[j] = r[j] + a * sg;
        }
        o.x = ov[0]; o.y = ov[1]; o.z = ov[2]; o.w = ov[3];
        *(float4*)&xout[(size_t)gr * DD + cb + tx * 4] = o;
    }
}

// ---------------------------------------------------------------------------
// Per-row squared norm of final encodings
// ---------------------------------------------------------------------------
__global__ void sqnorm_kernel(const float* __restrict__ x) {
    int row = blockIdx.x;
    int lane = threadIdx.x;  // 32 threads
    const float4* r4 = (const float4*)(x + (size_t)row * DD);
    float s = 0.f;
    #pragma unroll
    for (int i = 0; i < 2; ++i) {
        float4 v = r4[lane + i * 32];
        s += v.x*v.x + v.y*v.y + v.z*v.z + v.w*v.w;
    }
    #pragma unroll
    for (int o = 16; o; o >>= 1) s += __shfl_xor_sync(0xffffffffu, s, o);
    if (lane == 0) g_sq[row] = s;
}

// ---------------------------------------------------------------------------
// Fused: dot = art·tplT per batch, dist, S = exp(-dist)*am*tm, rowmax over T.
// grid (16 a-tiles, 16 batches); block computes 64 art rows vs all 512 tpl.
// ---------------------------------------------------------------------------
__global__ __launch_bounds__(256) void dist_rowmax_kernel(
    const float* __restrict__ x, const float* __restrict__ am, const float* __restrict__ tm)
{
    const int b = blockIdx.y;
    const int a0 = blockIdx.x << 6;
    const int tid = threadIdx.x, tx = tid & 15, ty = tid >> 4;

    __shared__ float arts[64][33];
    __shared__ float tps[64][33];
    __shared__ float a2s[64], ams[64], t2s[64], tms[64];
    __shared__ float red[64][17];

    const int abase = b * AA + a0;          // global row index (article region)
    const int tbase = NROWS_A + b * TT;     // global row index (template region)

    if (tid < 64) {
        a2s[tid] = g_sq[abase + tid];
        ams[tid] = am[b * AA + a0 + tid];
    }
    float lm[4] = {0.f, 0.f, 0.f, 0.f};     // S >= 0, so 0 is a valid identity

    for (int t0 = 0; t0 < TT; t0 += 64) {
        if (tid < 64) {
            t2s[tid] = g_sq[tbase + t0 + tid];
            tms[tid] = tm[b * TT + t0 + tid];
        }
        float acc[4][4] = {};
        for (int dc = 0; dc < DD; dc += 32) {
            #pragma unroll
            for (int s = 0; s < 8; ++s) {
                int e = tid + s * 256;
                int l = e >> 5, c = e & 31;
                arts[l][c] = x[(size_t)(abase + l) * DD + dc + c];
                tps[l][c]  = x[(size_t)(tbase + t0 + l) * DD + dc + c];
            }
            __syncthreads();
            #pragma unroll
            for (int dd = 0; dd < 32; ++dd) {
                float ar[4], tr[4];
                #pragma unroll
                for (int i = 0; i < 4; ++i) ar[i] = arts[ty * 4 + i][dd];
                #pragma unroll
                for (int j = 0; j < 4; ++j) tr[j] = tps[tx * 4 + j][dd];
                #pragma unroll
                for (int i = 0; i < 4; ++i)
                    #pragma unroll
                    for (int j = 0; j < 4; ++j)
                        acc[i][j] = fmaf(ar[i], tr[j], acc[i][j]);
            }
            __syncthreads();
        }
        #pragma unroll
        for (int i = 0; i < 4; ++i) {
            int r = ty * 4 + i;
            #pragma unroll
            for (int j = 0; j < 4; ++j) {
                int tj = tx * 4 + j;
                float dist = a2s[r] + t2s[tj] - 2.f * acc[i][j];
                dist = fmaxf(dist, 0.f);
                float S = expf(-dist) * ams[r] * tms[tj];
                lm[i] = fmaxf(lm[i], S);
            }
        }
        __syncthreads();  // protect t2s/tms before next chunk overwrites
    }

    #pragma unroll
    for (int i = 0; i < 4; ++i) red[ty * 4 + i][tx] = lm[i];
    __syncthreads();
    if (tid < 64) {
        float m = red[tid][0];
        #pragma unroll
        for (int xx = 1; xx < 16; ++xx) m = fmaxf(m, red[tid][xx]);
        g_rowmax[b * AA + a0 + tid] = m;
    }
}

// ---------------------------------------------------------------------------
// Top-10 (sorted desc, lowest-index tie break) + tiny 2-layer MLP -> out[b]
// ---------------------------------------------------------------------------
__global__ __launch_bounds__(256) void topk_ff_kernel(
    const float* __restrict__ f1w, const float* __restrict__ f1b,
    const float* __restrict__ f2w, const float* __restrict__ f2b,
    float* __restrict__ out)
{
    const int b = blockIdx.x;
    const int tid = threadIdx.x;
    __shared__ float vals[AA];
    __shared__ float sv[256];
    __shared__ int   si[256];
    __shared__ float top[10];

    #pragma unroll
    for (int s = 0; s < 4; ++s) vals[tid + s * 256] = g_rowmax[b * AA + tid + s * 256];
    __syncthreads();

    for (int it = 0; it < 10; ++it) {
        float v = -1.f; int idx = 1 << 20;
        #pragma unroll
        for (int s = 0; s < 4; ++s) {
            int i = s * 256 + tid;
            float xv = vals[i];
            if (xv > v || (xv == v && i < idx)) { v = xv; idx = i; }
        }
        sv[tid] = v; si[tid] = idx;
        __syncthreads();
        for (int o = 128; o; o >>= 1) {
            if (tid < o) {
                if (sv[tid+o] > sv[tid] || (sv[tid+o] == sv[tid] && si[tid+o] < si[tid])) {
                    sv[tid] = sv[tid+o]; si[tid] = si[tid+o];
                }
            }
            __syncthreads();
        }
        if (tid == 0) { top[it] = sv[0]; vals[si[0]] = -1.f; }
        __syncthreads();
    }

    if (tid == 0) {
        float o = f2b[0];
        #pragma unroll
        for (int j = 0; j < 10; ++j) {
            float h = f1b[j];
            #pragma unroll
            for (int i = 0; i < 10; ++i) h += top[i] * f1w[i * 10 + j];
            h = fmaxf(h, 0.f);
            o += h * f2w[j];
        }
        out[b] = o;
    }
}

// ---------------------------------------------------------------------------
// Launch
// ---------------------------------------------------------------------------
extern "C" void kernel_launch(void* const* d_in, const int* in_sizes, int n_in,
                              void* d_out, int out_size) {
    const int*   aw    = (const int*)d_in[0];
    const int*   tw    = (const int*)d_in[2];
    const float* am    = (const float*)d_in[4];
    const float* tm    = (const float*)d_in[5];
    const float* emb   = (const float*)d_in[6];
    const float* exp_w = (const float*)d_in[7];
    const float* exp_b = (const float*)d_in[8];
    const float* ref_w = (const float*)d_in[9];
    const float* ref_b = (const float*)d_in[10];
    const float* f1w   = (const float*)d_in[11];
    const float* f1b   = (const float*)d_in[12];
    const float* f2w   = (const float*)d_in[13];
    const float* f2b   = (const float*)d_in[14];
    float* out = (float*)d_out;

    float *b0 = nullptr, *b1 = nullptr;
    cudaGetSymbolAddress((void**)&b0, g_buf0);
    cudaGetSymbolAddress((void**)&b1, g_buf1);

    embed_kernel<<<(NROWS * 64) / 256, 256>>>(aw, tw, emb);

    const int dils[10] = {1, 2, 4, 8, 16, 32, 32, 1, 1, 1};
    float* src = b0;
    float* dst = b1;
    for (int i = 0; i < 10; ++i) {
        const float* w  = (i < 7) ? exp_w + (size_t)i * 3 * DD * TWOD
                                  : ref_w + (size_t)(i - 7) * 3 * DD * TWOD;
        const float* bs = (i < 7) ? exp_b + i * TWOD : ref_b + (i - 7) * TWOD;
        conv_glu_kernel<<<dim3(384, 4), 256>>>(src, dst, w, bs, dils[i]);
        float* tmp = src; src = dst; dst = tmp;
    }
    // 10 swaps (even) -> final encodings are back in b0 == src
    sqnorm_kernel<<<NROWS, 32>>>(src);
    dist_rowmax_kernel<<<dim3(16, 16), 256>>>(src, am, tm);
    topk_ff_kernel<<<16, 256>>>(f1w, f1b, f2w, f2b, out);
}